// round 1
// baseline (speedup 1.0000x reference)
#include <cuda_runtime.h>

#define Bq   256
#define Tq   1024
#define NUMq 126
#define LBLq 128
#define NSM  152   // GB300 SM count: blocks bid and bid+NSM land on the same SM

__device__ int d_perm[Bq];

// Rank sequences by length (descending, ties by index) so we can pair
// long sequences with short ones on the same SM.
__global__ void rank_kernel(const int* __restrict__ lens) {
    __shared__ int sl[Bq];
    int i = threadIdx.x;
    int li = lens[i];
    sl[i] = li;
    __syncthreads();
    int r = 0;
    #pragma unroll 8
    for (int k = 0; k < Bq; ++k) {
        int lk = sl[k];
        r += (lk > li) || (lk == li && k < i);
    }
    d_perm[r] = i;
}

__global__ __launch_bounds__(128, 2)
void crf_kernel(const float* __restrict__ logits,
                const int*   __restrict__ labels,
                const int*   __restrict__ lens,
                const float* __restrict__ trans,
                float*       __restrict__ out) {
    const int bid = blockIdx.x;
    // blocks [0,NSM) take the longest ranks; blocks [NSM,256) take the
    // shortest ranks in reverse so each SM's pair sums to ~max_len steps.
    const int slot = (bid < NSM) ? bid : (Bq - 1 - (bid - NSM));
    const int b    = d_perm[slot];
    const int len  = lens[b];
    const int j    = threadIdx.x;
    const int wid  = j >> 5;
    const int lid  = j & 31;

    __shared__ __align__(16) float abuf[2][LBLq];  // linear alpha, double buffered
    __shared__ float part[2][4];                   // per-warp normalizer partials
    __shared__ float red[4];                       // misc reduction scratch

    // ---- expT row j into registers: R[k] = exp(trans[j][k]) ----
    float R[LBLq];
    {
        const float4* trow = (const float4*)(trans + j * LBLq);
        #pragma unroll
        for (int k4 = 0; k4 < LBLq / 4; ++k4) {
            float4 v = trow[k4];
            R[4 * k4 + 0] = __expf(v.x);
            R[4 * k4 + 1] = __expf(v.y);
            R[4 * k4 + 2] = __expf(v.z);
            R[4 * k4 + 3] = __expf(v.w);
        }
    }

    // ---- gold path score (cooperative, strided over t) ----
    const int lb = b * Tq;
    const float* lgb = logits + (size_t)lb * NUMq;
    float g = 0.f;
    for (int t = j; t < len; t += 128) {
        int lab = labels[lb + t];
        g += lgb[t * NUMq + lab];                       // unary
        int prev = (t == 0) ? (LBLq - 2) : labels[lb + t - 1];
        g += trans[lab * LBLq + prev];                  // binary
    }
    if (j == 0) g += trans[(LBLq - 1) * LBLq + labels[lb + len - 1]];  // into end
    g += __shfl_xor_sync(0xffffffffu, g, 16);
    g += __shfl_xor_sync(0xffffffffu, g, 8);
    g += __shfl_xor_sync(0xffffffffu, g, 4);
    g += __shfl_xor_sync(0xffffffffu, g, 2);
    g += __shfl_xor_sync(0xffffffffu, g, 1);
    if (lid == 0) red[wid] = g;
    __syncthreads();
    float gold = 0.f;
    if (j == 0) gold = (red[0] + red[1]) + (red[2] + red[3]);

    // ---- init: alpha0 = onehot(start=126) in linear space ----
    abuf[0][j] = (j == (LBLq - 2)) ? 1.0f : 0.0f;
    if (j < 4) part[1][j] = (j == 0) ? 1.0f : 0.0f;  // c_{-1} = 1

    const bool  active = (j < NUMq);
    const float* lgcol = lgb + j;
    float nxt  = active ? lgcol[0] : 0.f;   // prefetch logit for t=0 (len >= 1)
    float logc = 0.f;                        // accumulated log normalizer
    __syncthreads();

    // ---- scaled forward scan ----
    for (int t = 0; t < len; ++t) {
        const int rb = t & 1, wb = rb ^ 1;

        // previous step's normalizer (lazy: folded into this step's w)
        float total = (part[wb][0] + part[wb][1]) + (part[wb][2] + part[wb][3]);
        float inv   = __fdividef(1.0f, total);
        logc += __logf(total);

        float cur = nxt;
        if (active && (t + 1 < len)) nxt = lgcol[(t + 1) * NUMq];
        float w = active ? (__expf(cur) * inv) : 0.f;

        // dot: sum_k expT[j,k] * alpha[k]  (alpha reads are uniform broadcasts)
        const float4* aa = (const float4*)abuf[rb];
        float a0 = 0.f, a1 = 0.f, a2 = 0.f, a3 = 0.f;
        #pragma unroll
        for (int k4 = 0; k4 < LBLq / 4; ++k4) {
            float4 a = aa[k4];
            a0 = fmaf(R[4 * k4 + 0], a.x, a0);
            a1 = fmaf(R[4 * k4 + 1], a.y, a1);
            a2 = fmaf(R[4 * k4 + 2], a.z, a2);
            a3 = fmaf(R[4 * k4 + 3], a.w, a3);
        }
        float v = w * ((a0 + a1) + (a2 + a3));
        abuf[wb][j] = v;

        // normalizer for the NEXT step: c_t = sum_j v_j
        float s = v;
        s += __shfl_xor_sync(0xffffffffu, s, 16);
        s += __shfl_xor_sync(0xffffffffu, s, 8);
        s += __shfl_xor_sync(0xffffffffu, s, 4);
        s += __shfl_xor_sync(0xffffffffu, s, 2);
        s += __shfl_xor_sync(0xffffffffu, s, 1);
        if (lid == 0) part[rb][wid] = s;
        __syncthreads();
    }

    // ---- finish: alpha += trans[end], norm = logc + log(sum) ----
    const int rbf = len & 1;
    float fv = abuf[rbf][j] * __expf(trans[(LBLq - 1) * LBLq + j]);
    fv += __shfl_xor_sync(0xffffffffu, fv, 16);
    fv += __shfl_xor_sync(0xffffffffu, fv, 8);
    fv += __shfl_xor_sync(0xffffffffu, fv, 4);
    fv += __shfl_xor_sync(0xffffffffu, fv, 2);
    fv += __shfl_xor_sync(0xffffffffu, fv, 1);
    if (lid == 0) red[wid] = fv;
    __syncthreads();
    if (j == 0) {
        float fs = (red[0] + red[1]) + (red[2] + red[3]);
        out[b] = gold - (logc + __logf(fs));
    }
}

extern "C" void kernel_launch(void* const* d_in, const int* in_sizes, int n_in,
                              void* d_out, int out_size) {
    const float* logits = (const float*)d_in[0];
    const int*   labels = (const int*)d_in[1];
    const int*   lens   = (const int*)d_in[2];
    const float* trans  = (const float*)d_in[3];
    float*       out    = (float*)d_out;

    rank_kernel<<<1, Bq>>>(lens);
    crf_kernel<<<Bq, 128>>>(logits, labels, lens, trans, out);
}

// round 2
// speedup vs baseline: 1.5761x; 1.5761x over previous
#include <cuda_runtime.h>

#define Bq   256
#define Tq   1024
#define NUMq 126
#define LBLq 128
#define NSM  152   // blocks bid and bid+NSM land on the same SM (contiguous-modular)

__device__ int d_perm[Bq];

// Rank sequences by length (desc) so each SM's CTA pair sums to ~max_len steps.
__global__ void rank_kernel(const int* __restrict__ lens) {
    __shared__ int sl[Bq];
    int i = threadIdx.x;
    int li = lens[i];
    sl[i] = li;
    __syncthreads();
    int r = 0;
    #pragma unroll 8
    for (int k = 0; k < Bq; ++k) {
        int lk = sl[k];
        r += (lk > li) || (lk == li && k < i);
    }
    d_perm[r] = i;
}

__device__ __forceinline__ void fma2(unsigned long long& d,
                                     unsigned long long a, unsigned long long b) {
    asm("fma.rn.f32x2 %0, %1, %2, %0;" : "+l"(d) : "l"(a), "l"(b));
}
__device__ __forceinline__ unsigned long long add2(unsigned long long a,
                                                   unsigned long long b) {
    unsigned long long d;
    asm("add.rn.f32x2 %0, %1, %2;" : "=l"(d) : "l"(a), "l"(b));
    return d;
}
__device__ __forceinline__ unsigned long long pack2(float lo, float hi) {
    unsigned long long d;
    asm("mov.b64 %0, {%1, %2};" : "=l"(d) : "f"(lo), "f"(hi));
    return d;
}
__device__ __forceinline__ void unpack2(unsigned long long d, float& lo, float& hi) {
    asm("mov.b64 {%0, %1}, %2;" : "=f"(lo), "=f"(hi) : "l"(d));
}

__global__ __launch_bounds__(128, 2)
void crf_kernel(const float* __restrict__ logits,
                const int*   __restrict__ labels,
                const int*   __restrict__ lens,
                const float* __restrict__ trans,
                float*       __restrict__ out) {
    const int bid = blockIdx.x;
    const int slot = (bid < NSM) ? bid : (Bq - 1 - (bid - NSM));
    const int b    = d_perm[slot];
    const int len  = lens[b];
    const int j    = threadIdx.x;
    const int wid  = j >> 5;
    const int lid  = j & 31;

    __shared__ __align__(16) float abuf[2][LBLq];  // linear alpha, double buffered
    __shared__ float part[4];                      // per-warp normalizer partials
    __shared__ float red[4];                       // misc reduction scratch

    // ---- expT row j, packed into 64 f32x2 registers ----
    unsigned long long R2[LBLq / 2];
    {
        const float4* trow = (const float4*)(trans + j * LBLq);
        #pragma unroll
        for (int k4 = 0; k4 < LBLq / 4; ++k4) {
            float4 v = trow[k4];
            R2[2 * k4 + 0] = pack2(__expf(v.x), __expf(v.y));
            R2[2 * k4 + 1] = pack2(__expf(v.z), __expf(v.w));
        }
    }

    // ---- gold path score (cooperative over t) ----
    const int lb = b * Tq;
    const float* lgb = logits + (size_t)lb * NUMq;
    float g = 0.f;
    for (int t = j; t < len; t += 128) {
        int lab = labels[lb + t];
        g += lgb[t * NUMq + lab];                       // unary
        int prev = (t == 0) ? (LBLq - 2) : labels[lb + t - 1];
        g += trans[lab * LBLq + prev];                  // binary
    }
    if (j == 0) g += trans[(LBLq - 1) * LBLq + labels[lb + len - 1]];  // into end
    g += __shfl_xor_sync(0xffffffffu, g, 16);
    g += __shfl_xor_sync(0xffffffffu, g, 8);
    g += __shfl_xor_sync(0xffffffffu, g, 4);
    g += __shfl_xor_sync(0xffffffffu, g, 2);
    g += __shfl_xor_sync(0xffffffffu, g, 1);
    if (lid == 0) red[wid] = g;
    __syncthreads();
    float gold = 0.f;
    if (j == 0) gold = (red[0] + red[1]) + (red[2] + red[3]);

    // ---- init: alpha0 = onehot(start=126) in linear space ----
    abuf[0][j] = (j == (LBLq - 2)) ? 1.0f : 0.0f;
    if (j < 4) part[j] = (j == 0) ? 1.0f : 0.0f;  // virtual c_{-1} = 1

    const bool   active = (j < NUMq);
    const float* lgcol  = lgb + j;

    // logit queues: current group's 4 and next group's 4
    float curq[4], nxtq[4];
    #pragma unroll
    for (int q = 0; q < 4; ++q)
        curq[q] = (active && q < len) ? lgcol[q * NUMq] : 0.f;
    #pragma unroll
    for (int q = 0; q < 4; ++q)
        nxtq[q] = (active && (4 + q) < len) ? lgcol[(4 + q) * NUMq] : 0.f;

    float logc = 0.f;
    float inv  = 1.0f;
    __syncthreads();

    // ---- scaled forward scan, normalization amortized over groups of 4 ----
    for (int t = 0; t < len; ++t) {
        const int ph = t & 3;
        const int rb = t & 1, wb = rb ^ 1;

        if (ph == 0) {
            float total = (part[0] + part[1]) + (part[2] + part[3]);
            inv  = __fdividef(1.0f, total);
            logc += __logf(total);
            if (t) {
                #pragma unroll
                for (int q = 0; q < 4; ++q) curq[q] = nxtq[q];
                #pragma unroll
                for (int q = 0; q < 4; ++q)
                    nxtq[q] = (active && (t + 4 + q) < len) ? lgcol[(t + 4 + q) * NUMq] : 0.f;
            }
        }

        float w = active ? __expf(curq[ph]) : 0.f;
        if (ph == 0) w *= inv;

        // dot: sum_k expT[j,k] * alpha[k]  — packed f32x2, 8 accumulators
        const ulonglong2* aa = (const ulonglong2*)abuf[rb];
        unsigned long long acc[8];
        #pragma unroll
        for (int k = 0; k < 8; ++k) acc[k] = 0ull;
        #pragma unroll
        for (int kk = 0; kk < 32; ++kk) {
            ulonglong2 a = aa[kk];
            fma2(acc[(2 * kk) & 7],     R2[2 * kk],     a.x);
            fma2(acc[(2 * kk + 1) & 7], R2[2 * kk + 1], a.y);
        }
        unsigned long long s01 = add2(acc[0], acc[1]);
        unsigned long long s23 = add2(acc[2], acc[3]);
        unsigned long long s45 = add2(acc[4], acc[5]);
        unsigned long long s67 = add2(acc[6], acc[7]);
        unsigned long long sA  = add2(s01, s23);
        unsigned long long sB  = add2(s45, s67);
        unsigned long long sT  = add2(sA, sB);
        float lo, hi;
        unpack2(sT, lo, hi);
        float v = w * (lo + hi);
        abuf[wb][j] = v;

        // normalizer for the next group (only at group tails that matter)
        if (ph == 3 && (t + 1 < len)) {
            float s = v;
            s += __shfl_xor_sync(0xffffffffu, s, 16);
            s += __shfl_xor_sync(0xffffffffu, s, 8);
            s += __shfl_xor_sync(0xffffffffu, s, 4);
            s += __shfl_xor_sync(0xffffffffu, s, 2);
            s += __shfl_xor_sync(0xffffffffu, s, 1);
            if (lid == 0) part[wid] = s;
        }
        __syncthreads();
    }

    // ---- finish: alpha *= exp(trans[end]), norm = logc + log(sum) ----
    const int rbf = len & 1;
    float fv = abuf[rbf][j] * __expf(trans[(LBLq - 1) * LBLq + j]);
    fv += __shfl_xor_sync(0xffffffffu, fv, 16);
    fv += __shfl_xor_sync(0xffffffffu, fv, 8);
    fv += __shfl_xor_sync(0xffffffffu, fv, 4);
    fv += __shfl_xor_sync(0xffffffffu, fv, 2);
    fv += __shfl_xor_sync(0xffffffffu, fv, 1);
    if (lid == 0) red[wid] = fv;
    __syncthreads();
    if (j == 0) {
        float fs = (red[0] + red[1]) + (red[2] + red[3]);
        out[b] = gold - (logc + __logf(fs));
    }
}

extern "C" void kernel_launch(void* const* d_in, const int* in_sizes, int n_in,
                              void* d_out, int out_size) {
    const float* logits = (const float*)d_in[0];
    const int*   labels = (const int*)d_in[1];
    const int*   lens   = (const int*)d_in[2];
    const float* trans  = (const float*)d_in[3];
    float*       out    = (float*)d_out;

    rank_kernel<<<1, Bq>>>(lens);
    crf_kernel<<<Bq, 128>>>(logits, labels, lens, trans, out);
}